// round 1
// baseline (speedup 1.0000x reference)
#include <cuda_runtime.h>

// Scratch for per-token segment ranges (T = 132096 in this problem; headroom).
#define MAX_T 140000
__device__ int g_seg_start[MAX_T];
__device__ int g_seg_end[MAX_T];

// Segments belonging to one token are contiguous in seg_token_idx (it is built
// by repeat(token_rank, segs_per_token)), though token ids are NOT sorted.
// Detect run boundaries and scatter start/end per token.
__global__ void seg_bounds_kernel(const int* __restrict__ idx, int S) {
    int i = blockIdx.x * blockDim.x + threadIdx.x;
    if (i >= S) return;
    int t = idx[i];
    if (i == 0 || idx[i - 1] != t) g_seg_start[t] = i;
    if (i == S - 1 || idx[i + 1] != t) g_seg_end[t] = i + 1;
}

// Fused segment-sum + GEMM.
// Block: 256 threads handles 32 tokens x 512 H outputs.
// smem: W[32][512] (64KB) + b[512] (2KB) + tok[32][32] (4KB) = 70KB dynamic.
__global__ __launch_bounds__(256) void fused_segsum_gemm_kernel(
    const float* __restrict__ features,   // [S, 32]
    const float* __restrict__ W,          // [32, 512]
    const float* __restrict__ b,          // [512]
    float* __restrict__ out,              // [T, 512]
    int T)
{
    extern __shared__ float smem[];
    float* sW   = smem;                 // 32*512 floats
    float* sB   = sW + 32 * 512;        // 512 floats
    float* sTok = sB + 512;             // 32*32 floats

    const int tid = threadIdx.x;

    // --- Stage W and b into shared (float4, coalesced) ---
    {
        float4* sW4 = reinterpret_cast<float4*>(sW);
        const float4* W4 = reinterpret_cast<const float4*>(W);
        #pragma unroll
        for (int i = tid; i < 32 * 128; i += 256) sW4[i] = W4[i];
        if (tid < 128)
            reinterpret_cast<float4*>(sB)[tid] =
                reinterpret_cast<const float4*>(b)[tid];
    }

    const int block_token = blockIdx.x * 32;

    // --- Per-token feature sums into smem ---
    // tid -> (token-lane tl, feature f); warp lanes cover f=0..31 of one token
    // so the feature loads are fully coalesced (consecutive 4B addresses).
    {
        const int f   = tid & 31;
        const int tl0 = tid >> 5;        // 0..7
        #pragma unroll
        for (int tl = tl0; tl < 32; tl += 8) {
            int tok = block_token + tl;
            float s = 1e-10f;            // reference adds 1e-10 to token sums
            if (tok < T) {
                int s0 = g_seg_start[tok];
                int s1 = g_seg_end[tok];
                for (int si = s0; si < s1; si++)
                    s += features[(size_t)si * 32 + f];
            }
            sTok[tl * 32 + f] = s;
        }
    }
    __syncthreads();

    // --- Register-blocked GEMM: each thread owns 4 consecutive H columns
    //     (one float4) for 16 tokens (two groups of 128 threads x 16 tokens).
    const int group = tid >> 7;          // 0 or 1
    const int hc    = tid & 127;         // float4 column index (H/4 = 128)
    const float4 bv = reinterpret_cast<float4*>(sB)[hc];
    const float4* sW4 = reinterpret_cast<const float4*>(sW);

    #pragma unroll 1
    for (int c = 0; c < 16; c += 4) {
        const int tb = group * 16 + c;   // local token base of this 4-chunk
        float4 a0 = bv, a1 = bv, a2 = bv, a3 = bv;

        #pragma unroll
        for (int f = 0; f < 32; f++) {
            // LDS.128, conflict-free (consecutive lanes -> consecutive 16B)
            float4 w = sW4[f * 128 + hc];
            // broadcast LDS (all lanes in a group read the same word)
            float t0 = sTok[(tb + 0) * 32 + f];
            float t1 = sTok[(tb + 1) * 32 + f];
            float t2 = sTok[(tb + 2) * 32 + f];
            float t3 = sTok[(tb + 3) * 32 + f];
            a0.x += t0 * w.x; a0.y += t0 * w.y; a0.z += t0 * w.z; a0.w += t0 * w.w;
            a1.x += t1 * w.x; a1.y += t1 * w.y; a1.z += t1 * w.z; a1.w += t1 * w.w;
            a2.x += t2 * w.x; a2.y += t2 * w.y; a2.z += t2 * w.z; a2.w += t2 * w.w;
            a3.x += t3 * w.x; a3.y += t3 * w.y; a3.z += t3 * w.z; a3.w += t3 * w.w;
        }

        // Coalesced float4 stores (128 lanes cover one 2KB output row)
        const int tok = block_token + tb;
        float4* out4 = reinterpret_cast<float4*>(out);
        if (tok + 0 < T) out4[(size_t)(tok + 0) * 128 + hc] = a0;
        if (tok + 1 < T) out4[(size_t)(tok + 1) * 128 + hc] = a1;
        if (tok + 2 < T) out4[(size_t)(tok + 2) * 128 + hc] = a2;
        if (tok + 3 < T) out4[(size_t)(tok + 3) * 128 + hc] = a3;
    }
}

extern "C" void kernel_launch(void* const* d_in, const int* in_sizes, int n_in,
                              void* d_out, int out_size) {
    const float* features = (const float*)d_in[0];   // [S, 32]
    const float* W        = (const float*)d_in[1];   // [32, 512]
    const float* b        = (const float*)d_in[2];   // [512]
    const int*   idx      = (const int*)d_in[3];     // [S]
    float*       out      = (float*)d_out;           // [T, 512]

    const int S = in_sizes[3];
    const int T = out_size / 512;

    // Allow 70KB dynamic smem (idempotent; safe under graph capture)
    static bool attr_set = false;
    if (!attr_set) {
        cudaFuncSetAttribute(fused_segsum_gemm_kernel,
                             cudaFuncAttributeMaxDynamicSharedMemorySize,
                             (32 * 512 + 512 + 32 * 32) * (int)sizeof(float));
        attr_set = true;
    }

    seg_bounds_kernel<<<(S + 255) / 256, 256>>>(idx, S);

    const int smem_bytes = (32 * 512 + 512 + 32 * 32) * (int)sizeof(float);
    fused_segsum_gemm_kernel<<<(T + 31) / 32, 256, smem_bytes>>>(
        features, W, b, out, T);
}

// round 2
// speedup vs baseline: 1.5510x; 1.5510x over previous
#include <cuda_runtime.h>

// Scratch for per-token segment ranges (T = 132096 here; headroom).
#define MAX_T 140000
__device__ int g_seg_start[MAX_T];
__device__ int g_seg_end[MAX_T];

// Segments of one token are contiguous in seg_token_idx (built by
// repeat(token_rank, segs_per_token)); token ids are NOT sorted, so we
// scatter run boundaries.
__global__ void seg_bounds_kernel(const int* __restrict__ idx, int S) {
    int i = blockIdx.x * blockDim.x + threadIdx.x;
    if (i >= S) return;
    int t = idx[i];
    if (i == 0 || idx[i - 1] != t) g_seg_start[t] = i;
    if (i == S - 1 || idx[i + 1] != t) g_seg_end[t] = i + 1;
}

// Packed dual-FMA: (d.x,d.y) += (a.x,a.y)*(b.x,b.y).  ptxas never emits
// FFMA2 from C++; PTX fma.rn.f32x2 is required (2 FMAs per issue slot,
// vs half-rate 3-reg FFMA).
__device__ __forceinline__ void fma2(float2& d, const float2 a, const float2 b) {
    asm("fma.rn.f32x2 %0, %1, %2, %0;"
        : "+l"(reinterpret_cast<unsigned long long&>(d))
        : "l"(reinterpret_cast<const unsigned long long&>(a)),
          "l"(reinterpret_cast<const unsigned long long&>(b)));
}

#define TOK_STRIDE 34   // padded floats per f-row of the token tile

// Fused segment-sum + GEMM.  256 threads, 32 tokens/block.
// smem: W[32][512] (64KB) + tokT[32][34] (4.25KB).
__global__ __launch_bounds__(256, 2) void fused_segsum_gemm_kernel(
    const float* __restrict__ features,   // [S, 32]
    const float* __restrict__ W,          // [32, 512]
    const float* __restrict__ b,          // [512]
    float* __restrict__ out,              // [T, 512]
    int T)
{
    extern __shared__ float smem[];
    float* sW = smem;                  // 32*512
    float* sT = smem + 32 * 512;       // 32*TOK_STRIDE, transposed [f][tok]

    const int tid = threadIdx.x;

    // --- Stage W (float4, coalesced) ---
    {
        float4* sW4w = reinterpret_cast<float4*>(sW);
        const float4* W4 = reinterpret_cast<const float4*>(W);
        #pragma unroll
        for (int i = tid; i < 32 * 128; i += 256) sW4w[i] = W4[i];
    }

    const int block_token = blockIdx.x * 32;

    // --- Per-token feature sums -> transposed smem tile sT[f][tl] ---
    // Warp lanes cover f=0..31 of one token: coalesced gmem reads; the
    // transposed STS is only 2-way bank conflicted (stride 34).
    {
        const int f   = tid & 31;
        const int tl0 = tid >> 5;      // 0..7
        #pragma unroll
        for (int tl = tl0; tl < 32; tl += 8) {
            int tok = block_token + tl;
            float s = 1e-10f;          // reference adds 1e-10 to token sums
            if (tok < T) {
                int s0 = g_seg_start[tok];
                int s1 = g_seg_end[tok];
                for (int si = s0; si < s1; si++)
                    s += features[(size_t)si * 32 + f];
            }
            sT[f * TOK_STRIDE + tl] = s;
        }
    }
    __syncthreads();

    // --- GEMM: thread owns 4 consecutive H cols (hc) x 16 tokens (group).
    // Token pairs load as natural float2 broadcasts; W value dup'd into
    // both halves so each fma.rn.f32x2 does 2 tokens at once.
    const int hc    = tid & 127;       // float4 column (H/4 = 128)
    const int group = tid >> 7;        // 0 or 1 -> tokens [0,16) or [16,32)
    const float4* sW4 = reinterpret_cast<const float4*>(sW);
    const float2* sT2 = reinterpret_cast<const float2*>(sT);
    const int tbase2 = group * 8;      // float2 offset within an f-row

    const float4 bv = reinterpret_cast<const float4*>(b)[hc];
    float2 acc[8][4];
    #pragma unroll
    for (int p = 0; p < 8; p++) {
        acc[p][0] = make_float2(bv.x, bv.x);
        acc[p][1] = make_float2(bv.y, bv.y);
        acc[p][2] = make_float2(bv.z, bv.z);
        acc[p][3] = make_float2(bv.w, bv.w);
    }

    #pragma unroll 4
    for (int f = 0; f < 32; f++) {
        const float4 w = sW4[f * 128 + hc];          // LDS.128, conflict-free
        const float2 wx = make_float2(w.x, w.x);
        const float2 wy = make_float2(w.y, w.y);
        const float2 wz = make_float2(w.z, w.z);
        const float2 ww = make_float2(w.w, w.w);
        const float2* row = sT2 + f * (TOK_STRIDE / 2) + tbase2;
        #pragma unroll
        for (int p = 0; p < 8; p++) {
            const float2 t = row[p];                 // broadcast LDS.64
            fma2(acc[p][0], t, wx);
            fma2(acc[p][1], t, wy);
            fma2(acc[p][2], t, wz);
            fma2(acc[p][3], t, ww);
        }
    }

    // --- Coalesced float4 stores ---
    const int tok0 = block_token + group * 16;
    float4* out4 = reinterpret_cast<float4*>(out);
    #pragma unroll
    for (int p = 0; p < 8; p++) {
        int t0 = tok0 + 2 * p;
        if (t0 < T)
            out4[(size_t)t0 * 128 + hc] =
                make_float4(acc[p][0].x, acc[p][1].x, acc[p][2].x, acc[p][3].x);
        if (t0 + 1 < T)
            out4[(size_t)(t0 + 1) * 128 + hc] =
                make_float4(acc[p][0].y, acc[p][1].y, acc[p][2].y, acc[p][3].y);
    }
}

extern "C" void kernel_launch(void* const* d_in, const int* in_sizes, int n_in,
                              void* d_out, int out_size) {
    const float* features = (const float*)d_in[0];   // [S, 32]
    const float* W        = (const float*)d_in[1];   // [32, 512]
    const float* b        = (const float*)d_in[2];   // [512]
    const int*   idx      = (const int*)d_in[3];     // [S]
    float*       out      = (float*)d_out;           // [T, 512]

    const int S = in_sizes[3];
    const int T = out_size / 512;

    const int smem_bytes = (32 * 512 + 32 * TOK_STRIDE) * (int)sizeof(float);
    static bool attr_set = false;
    if (!attr_set) {
        cudaFuncSetAttribute(fused_segsum_gemm_kernel,
                             cudaFuncAttributeMaxDynamicSharedMemorySize,
                             smem_bytes);
        attr_set = true;
    }

    seg_bounds_kernel<<<(S + 255) / 256, 256>>>(idx, S);
    fused_segsum_gemm_kernel<<<(T + 31) / 32, 256, smem_bytes>>>(
        features, W, b, out, T);
}

// round 3
// speedup vs baseline: 1.8085x; 1.1660x over previous
#include <cuda_runtime.h>

// Scratch for per-token segment ranges (T = 132096 here; headroom).
#define MAX_T 140000
__device__ int g_seg_start[MAX_T];
__device__ int g_seg_end[MAX_T];

// Segments of one token are contiguous in seg_token_idx (built by
// repeat(token_rank, segs_per_token)); token ids are NOT sorted, so we
// scatter run boundaries.
__global__ void seg_bounds_kernel(const int* __restrict__ idx, int S) {
    int i = blockIdx.x * blockDim.x + threadIdx.x;
    if (i >= S) return;
    int t = idx[i];
    if (i == 0 || idx[i - 1] != t) g_seg_start[t] = i;
    if (i == S - 1 || idx[i + 1] != t) g_seg_end[t] = i + 1;
}

// Packed dual-FMA (PTX-only; ptxas never fuses to FFMA2 from C++).
__device__ __forceinline__ void fma2(float2& d, const float2 a, const float2 b) {
    asm("fma.rn.f32x2 %0, %1, %2, %0;"
        : "+l"(reinterpret_cast<unsigned long long&>(d))
        : "l"(reinterpret_cast<const unsigned long long&>(a)),
          "l"(reinterpret_cast<const unsigned long long&>(b)));
}

#define TOKS 32
#define TSTR 36   // floats per f-row of token tile: 144B, 16B-aligned rows

// Persistent fused segment-sum + GEMM.
// 256 threads, 2 CTAs/SM. Each CTA loops over 32-token tiles, double-buffering
// the token tile in smem and prefetching the next tile's gather (<=3 predicated
// independent LDGs per token-feature) across the GEMM of the current tile.
// smem: W[32][512] (64KB) + 2 x tokT[32][TSTR] (9KB).
__global__ __launch_bounds__(256, 2) void fused_persistent_kernel(
    const float* __restrict__ features,   // [S, 32]
    const float* __restrict__ W,          // [32, 512]
    const float* __restrict__ b,          // [512]
    float* __restrict__ out,              // [T, 512]
    int T, int ntiles)
{
    extern __shared__ float smem[];
    float* sW  = smem;                    // 32*512
    float* sT0 = smem + 32 * 512;         // buffer 0: 32*TSTR
    float* sT1 = sT0 + 32 * TSTR;         // buffer 1

    const int tid = threadIdx.x;
    const int f   = tid & 31;             // gather: feature lane (coalesced)
    const int tl0 = tid >> 5;             // gather: token base 0..7
    const int hc  = tid & 127;            // GEMM: float4 H column
    const int grp = tid >> 7;             // GEMM: token half (0/1)

    // --- Stage W once per CTA (float4, coalesced) ---
    {
        float4* d4 = reinterpret_cast<float4*>(sW);
        const float4* s4 = reinterpret_cast<const float4*>(W);
        #pragma unroll
        for (int i = tid; i < 32 * 128; i += 256) d4[i] = s4[i];
    }
    const float4 bv = reinterpret_cast<const float4*>(b)[hc];

    int tile = blockIdx.x;
    if (tile >= ntiles) return;

    float v0[4], v1[4], v2[4], ex[4];

    // Gather loads for a tile into registers: up to 3 independent predicated
    // LDGs per (token, f); rare n>3 handled by a cold loop.
    auto gather_loads = [&](int t_) {
        const int tok_base = t_ * TOKS;
        #pragma unroll
        for (int j = 0; j < 4; j++) {
            const int tok = tok_base + tl0 + 8 * j;
            int s0 = 0, n = 0;
            if (tok < T) {
                s0 = g_seg_start[tok];
                n  = g_seg_end[tok] - s0;
            }
            const float* p = features + (size_t)s0 * 32 + f;
            v0[j] = (n > 0) ? p[0]  : 0.0f;
            v1[j] = (n > 1) ? p[32] : 0.0f;
            v2[j] = (n > 2) ? p[64] : 0.0f;
            ex[j] = 0.0f;
            if (n > 3)
                for (int si = 3; si < n; si++) ex[j] += p[32 * si];
        }
    };
    // Reduce prefetched values and store the transposed token tile.
    auto reduce_sts = [&](float* buf) {
        #pragma unroll
        for (int j = 0; j < 4; j++)
            buf[f * TSTR + tl0 + 8 * j] =
                1e-10f + ((v0[j] + v1[j]) + (v2[j] + ex[j]));
    };

    // Prime the pipeline: gather tile 0 into buffer 0.
    gather_loads(tile);
    reduce_sts(sT0);
    __syncthreads();

    int buf = 0;
    while (true) {
        const int next = tile + gridDim.x;
        const bool has_next = next < ntiles;

        // Prefetch next tile's gather (independent LDGs, consumed after GEMM).
        if (has_next) gather_loads(next);

        // --- GEMM on current buffer: 16 tokens x 4 H cols per thread ---
        const float* bufc = (buf == 0) ? sT0 : sT1;
        const float* base = bufc + grp * 16;
        const float4* sW4 = reinterpret_cast<const float4*>(sW);

        float2 acc[8][4];
        #pragma unroll
        for (int p = 0; p < 8; p++) {
            acc[p][0] = make_float2(bv.x, bv.x);
            acc[p][1] = make_float2(bv.y, bv.y);
            acc[p][2] = make_float2(bv.z, bv.z);
            acc[p][3] = make_float2(bv.w, bv.w);
        }

        #pragma unroll 4
        for (int ff = 0; ff < 32; ff++) {
            const float4 w = sW4[ff * 128 + hc];        // LDS.128 conflict-free
            const float2 wx = make_float2(w.x, w.x);
            const float2 wy = make_float2(w.y, w.y);
            const float2 wz = make_float2(w.z, w.z);
            const float2 ww = make_float2(w.w, w.w);
            const float4* trow =
                reinterpret_cast<const float4*>(base + ff * TSTR);
            #pragma unroll
            for (int q = 0; q < 4; q++) {
                const float4 t = trow[q];               // broadcast LDS.128
                const float2 t01 = make_float2(t.x, t.y);
                const float2 t23 = make_float2(t.z, t.w);
                fma2(acc[2 * q + 0][0], t01, wx);
                fma2(acc[2 * q + 0][1], t01, wy);
                fma2(acc[2 * q + 0][2], t01, wz);
                fma2(acc[2 * q + 0][3], t01, ww);
                fma2(acc[2 * q + 1][0], t23, wx);
                fma2(acc[2 * q + 1][1], t23, wy);
                fma2(acc[2 * q + 1][2], t23, wz);
                fma2(acc[2 * q + 1][3], t23, ww);
            }
        }

        // --- Coalesced float4 stores ---
        {
            const int tok0 = tile * TOKS + grp * 16;
            float4* out4 = reinterpret_cast<float4*>(out);
            #pragma unroll
            for (int p = 0; p < 8; p++) {
                const int t0 = tok0 + 2 * p;
                if (t0 < T)
                    out4[(size_t)t0 * 128 + hc] = make_float4(
                        acc[p][0].x, acc[p][1].x, acc[p][2].x, acc[p][3].x);
                if (t0 + 1 < T)
                    out4[(size_t)(t0 + 1) * 128 + hc] = make_float4(
                        acc[p][0].y, acc[p][1].y, acc[p][2].y, acc[p][3].y);
            }
        }

        // Write next tile's sums into the other buffer, then sync.
        if (has_next) reduce_sts((buf == 0) ? sT1 : sT0);
        __syncthreads();
        if (!has_next) break;
        tile = next;
        buf ^= 1;
    }
}

extern "C" void kernel_launch(void* const* d_in, const int* in_sizes, int n_in,
                              void* d_out, int out_size) {
    const float* features = (const float*)d_in[0];   // [S, 32]
    const float* W        = (const float*)d_in[1];   // [32, 512]
    const float* b        = (const float*)d_in[2];   // [512]
    const int*   idx      = (const int*)d_in[3];     // [S]
    float*       out      = (float*)d_out;           // [T, 512]

    const int S = in_sizes[3];
    const int T = out_size / 512;
    const int ntiles = (T + TOKS - 1) / TOKS;

    const int smem_bytes = (32 * 512 + 2 * 32 * TSTR) * (int)sizeof(float);

    static int nsm = 0;
    if (nsm == 0) {
        // First call is the (non-captured) correctness run; cached afterwards.
        cudaDeviceGetAttribute(&nsm, cudaDevAttrMultiProcessorCount, 0);
        if (nsm <= 0) nsm = 148;
        cudaFuncSetAttribute(fused_persistent_kernel,
                             cudaFuncAttributeMaxDynamicSharedMemorySize,
                             smem_bytes);
    }

    seg_bounds_kernel<<<(S + 255) / 256, 256>>>(idx, S);

    int grid = 2 * nsm;
    if (grid > ntiles) grid = ntiles;
    fused_persistent_kernel<<<grid, 256, smem_bytes>>>(
        features, W, b, out, T, ntiles);
}

// round 5
// speedup vs baseline: 1.9268x; 1.0654x over previous
#include <cuda_runtime.h>
#include <cuda_bf16.h>
#include <cstdint>

// ---------------------------------------------------------------------------
// Scratch for per-token segment ranges (T = 132096 here; headroom).
#define MAX_T 140000
__device__ int g_seg_start[MAX_T];
__device__ int g_seg_end[MAX_T];

// Segments of one token are contiguous in seg_token_idx (built by
// repeat(token_rank, segs_per_token)); token ids are NOT sorted.
__global__ void seg_bounds_kernel(const int* __restrict__ idx, int S) {
    int i = blockIdx.x * blockDim.x + threadIdx.x;
    if (i >= S) return;
    int t = idx[i];
    if (i == 0 || idx[i - 1] != t) g_seg_start[t] = i;
    if (i == S - 1 || idx[i + 1] != t) g_seg_end[t] = i + 1;
}

// ---------------------------------------------------------------------------
__device__ __forceinline__ uint32_t smem_to_u32(const void* p) {
    uint32_t a;
    asm("{ .reg .u64 t; cvta.to.shared.u64 t, %1; cvt.u32.u64 %0, t; }"
        : "=r"(a) : "l"(p));
    return a;
}
__device__ __forceinline__ void ldsm_x4(uint32_t* r, uint32_t addr) {
    asm volatile("ldmatrix.sync.aligned.m8n8.x4.shared.b16 {%0,%1,%2,%3}, [%4];"
                 : "=r"(r[0]), "=r"(r[1]), "=r"(r[2]), "=r"(r[3]) : "r"(addr));
}
__device__ __forceinline__ void ldsm_x2(uint32_t& r0, uint32_t& r1, uint32_t addr) {
    asm volatile("ldmatrix.sync.aligned.m8n8.x2.shared.b16 {%0,%1}, [%2];"
                 : "=r"(r0), "=r"(r1) : "r"(addr));
}
__device__ __forceinline__ void hmma16816(float& c0, float& c1, float& c2, float& c3,
                                          const uint32_t* a, uint32_t b0, uint32_t b1) {
    asm volatile(
        "mma.sync.aligned.m16n8k16.row.col.f32.bf16.bf16.f32 "
        "{%0,%1,%2,%3}, {%4,%5,%6,%7}, {%8,%9}, {%0,%1,%2,%3};"
        : "+f"(c0), "+f"(c1), "+f"(c2), "+f"(c3)
        : "r"(a[0]), "r"(a[1]), "r"(a[2]), "r"(a[3]), "r"(b0), "r"(b1));
}

// ---------------------------------------------------------------------------
// Split-bf16 GEMM: out[t][h] = sum_k A[t][k] * B[h][k], K = 96, where
//   A k-layout: [0:32)=th, [32:64)=th, [64:96)=tl   (tok = th + tl)
//   B k-layout: [0:32)=wh, [32:64)=wl, [64:96)=wh   (W   = wh + wl)
// giving th*wh + th*wl + tl*wh  (drops tl*wl ~ 2^-16 rel).
//
// smem rows padded to 104 bf16 (208 B): 52-word row stride makes 8-row
// ldmatrix address sets bank-conflict-free.
static constexpr int TILE_TOK = 128;
static constexpr int ROWB     = 208;                 // bytes per k-row
static constexpr int SW_OFF   = 0;                   // W-split: 512 rows
static constexpr int ST0      = 512 * ROWB;          // 106496
static constexpr int TBYTES   = TILE_TOK * ROWB;     // 26624
static constexpr int ST1      = ST0 + TBYTES;        // 133120
static constexpr int SMEM_TOTAL = ST1 + TBYTES;      // 159744

__global__ __launch_bounds__(256, 1) void fused_hmma_kernel(
    const float* __restrict__ features,   // [S, 32]
    const float* __restrict__ W,          // [32, 512]
    const float* __restrict__ b,          // [512]
    float* __restrict__ out,              // [T, 512]
    int T, int ntiles)
{
    extern __shared__ char smem[];
    const uint32_t smem_base = smem_to_u32(smem);
    const int tid  = threadIdx.x;
    const int wid  = tid >> 5;
    const int lane = tid & 31;

    // --- Stage W^T split into smem [h=512][k] (once per CTA) ---
    for (int idx = tid; idx < 32 * 512; idx += 256) {
        const int f = idx >> 9, h = idx & 511;       // coalesced LDG over h
        const float wv = W[idx];
        const __nv_bfloat16 hb = __float2bfloat16(wv);
        const __nv_bfloat16 lb = __float2bfloat16(wv - __bfloat162float(hb));
        char* row = smem + SW_OFF + h * ROWB;
        *(__nv_bfloat16*)(row + 2 * f)        = hb;  // wh
        *(__nv_bfloat16*)(row + 2 * (32 + f)) = lb;  // wl
        *(__nv_bfloat16*)(row + 2 * (64 + f)) = hb;  // wh
    }
    __syncthreads();

    // --- Hoist this warp's B fragments into registers (persistent) ---
    // Warp w owns h-slice [w*64, w*64+64): 8 n-tiles x 6 k-steps x 2 regs.
    const int wslice = wid * 64;
    uint32_t breg[8][6][2];
    {
        const uint32_t wb = smem_base + SW_OFF;
        #pragma unroll
        for (int nt = 0; nt < 8; nt++)
            #pragma unroll
            for (int ks = 0; ks < 6; ks++) {
                uint32_t addr = wb + (wslice + nt * 8 + (lane & 7)) * ROWB
                              + (ks * 16 + ((lane >> 3) & 1) * 8) * 2;
                ldsm_x2(breg[nt][ks][0], breg[nt][ks][1], addr);
            }
    }
    // Bias per n-tile: cols (lane&3)*2, +1 (rows r and r+8 share cols).
    float biasx[8], biasy[8];
    #pragma unroll
    for (int nt = 0; nt < 8; nt++) {
        const int col = wslice + nt * 8 + (lane & 3) * 2;
        biasx[nt] = b[col];
        biasy[nt] = b[col + 1];
    }

    int tile = blockIdx.x;
    if (tile >= ntiles) return;   // grid is clamped; defensive (uniform per CTA)

    // --- Gather: thread (f = lane, token row base = wid) ---
    const int f = lane, trow = wid;
    float ts[16];
    auto gather = [&](int tile_) {
        const int tok0 = tile_ * TILE_TOK;
        #pragma unroll
        for (int j = 0; j < 16; j++) {
            const int tok = tok0 + trow + 8 * j;
            int s0 = 0, n = 0;
            if (tok < T) { s0 = g_seg_start[tok]; n = g_seg_end[tok] - s0; }
            const float* p = features + (size_t)s0 * 32 + f;
            float a0 = (n > 0) ? p[0]  : 0.0f;
            float a1 = (n > 1) ? p[32] : 0.0f;
            float a2 = (n > 2) ? p[64] : 0.0f;
            float ex = 0.0f;
            for (int si = 3; si < n; si++) ex += p[32 * si];
            ts[j] = 1e-10f + ((a0 + a1) + (a2 + ex));
        }
    };
    auto convert_sts = [&](char* B) {
        #pragma unroll
        for (int j = 0; j < 16; j++) {
            const int r = trow + 8 * j;
            const __nv_bfloat16 hb = __float2bfloat16(ts[j]);
            const __nv_bfloat16 lb =
                __float2bfloat16(ts[j] - __bfloat162float(hb));
            char* row = B + r * ROWB;
            *(__nv_bfloat16*)(row + 2 * f)        = hb;  // th
            *(__nv_bfloat16*)(row + 2 * (32 + f)) = hb;  // th
            *(__nv_bfloat16*)(row + 2 * (64 + f)) = lb;  // tl
        }
    };

    // Prime the pipeline.
    gather(tile);
    convert_sts(smem + ST0);
    __syncthreads();

    int buf = 0;
    while (true) {
        const int next = tile + gridDim.x;
        const bool has_next = next < ntiles;

        // Prefetch next tile's gather LDGs (consumed after the MMA phase).
        if (has_next) gather(next);

        // --- MMA + store phase on current buffer ---
        const uint32_t cur = smem_base + (buf ? ST1 : ST0);
        const int tok0 = tile * TILE_TOK;
        const uint32_t arow0 = cur + (lane & 15) * ROWB + ((lane >> 4) * 8) * 2;

        #pragma unroll 1
        for (int m = 0; m < 8; m++) {
            uint32_t a[6][4];
            const uint32_t arow = arow0 + m * 16 * ROWB;
            #pragma unroll
            for (int ks = 0; ks < 6; ks++) ldsm_x4(a[ks], arow + ks * 32);

            const int r0  = tok0 + m * 16 + (lane >> 2);
            float2* o0 = reinterpret_cast<float2*>(
                out + (size_t)r0 * 512 + wslice + (lane & 3) * 2);
            float2* o1 = reinterpret_cast<float2*>(
                out + (size_t)(r0 + 8) * 512 + wslice + (lane & 3) * 2);
            const bool p0 = r0 < T, p1 = (r0 + 8) < T;

            #pragma unroll
            for (int nt = 0; nt < 8; nt++) {
                float c0 = biasx[nt], c1 = biasy[nt], c2 = c0, c3 = c1;
                #pragma unroll
                for (int ks = 0; ks < 6; ks++)
                    hmma16816(c0, c1, c2, c3, a[ks],
                              breg[nt][ks][0], breg[nt][ks][1]);
                if (p0) o0[nt * 4] = make_float2(c0, c1);
                if (p1) o1[nt * 4] = make_float2(c2, c3);
            }
        }

        // Write next tile's token buffer; one sync per tile.
        if (has_next) convert_sts(smem + (buf ? ST0 : ST1));
        __syncthreads();
        if (!has_next) break;
        tile = next;
        buf ^= 1;
    }
}

// ---------------------------------------------------------------------------
extern "C" void kernel_launch(void* const* d_in, const int* in_sizes, int n_in,
                              void* d_out, int out_size) {
    const float* features = (const float*)d_in[0];   // [S, 32]
    const float* W        = (const float*)d_in[1];   // [32, 512]
    const float* b        = (const float*)d_in[2];   // [512]
    const int*   idx      = (const int*)d_in[3];     // [S]
    float*       out      = (float*)d_out;           // [T, 512]

    const int S = in_sizes[3];
    const int T = out_size / 512;
    const int ntiles = (T + TILE_TOK - 1) / TILE_TOK;

    static int nsm = 0;
    if (nsm == 0) {
        // First call is the (non-captured) correctness run; cached afterwards.
        cudaDeviceGetAttribute(&nsm, cudaDevAttrMultiProcessorCount, 0);
        if (nsm <= 0) nsm = 148;
        cudaFuncSetAttribute(fused_hmma_kernel,
                             cudaFuncAttributeMaxDynamicSharedMemorySize,
                             SMEM_TOTAL);
    }

    seg_bounds_kernel<<<(S + 255) / 256, 256>>>(idx, S);

    int grid = nsm;
    if (grid > ntiles) grid = ntiles;
    fused_hmma_kernel<<<grid, 256, SMEM_TOTAL>>>(features, W, b, out, T, ntiles);
}

// round 6
// speedup vs baseline: 2.4419x; 1.2673x over previous
#include <cuda_runtime.h>
#include <cuda_bf16.h>
#include <cstdint>

// ---------------------------------------------------------------------------
// Scratch for per-token segment ranges (T = 132096 here; headroom).
#define MAX_T 140000
__device__ int g_seg_start[MAX_T];
__device__ int g_seg_end[MAX_T];

// Segments of one token are contiguous in seg_token_idx (built by
// repeat(token_rank, segs_per_token)); token ids are NOT sorted.
__global__ void seg_bounds_kernel(const int* __restrict__ idx, int S) {
    int i = blockIdx.x * blockDim.x + threadIdx.x;
    if (i >= S) return;
    int t = idx[i];
    if (i == 0 || idx[i - 1] != t) g_seg_start[t] = i;
    if (i == S - 1 || idx[i + 1] != t) g_seg_end[t] = i + 1;
}

// ---------------------------------------------------------------------------
__device__ __forceinline__ uint32_t smem_to_u32(const void* p) {
    uint32_t a;
    asm("{ .reg .u64 t; cvta.to.shared.u64 t, %1; cvt.u32.u64 %0, t; }"
        : "=r"(a) : "l"(p));
    return a;
}
__device__ __forceinline__ void ldsm_x4(uint32_t* r, uint32_t addr) {
    asm volatile("ldmatrix.sync.aligned.m8n8.x4.shared.b16 {%0,%1,%2,%3}, [%4];"
                 : "=r"(r[0]), "=r"(r[1]), "=r"(r[2]), "=r"(r[3]) : "r"(addr));
}
__device__ __forceinline__ void ldsm_x2(uint32_t& r0, uint32_t& r1, uint32_t addr) {
    asm volatile("ldmatrix.sync.aligned.m8n8.x2.shared.b16 {%0,%1}, [%2];"
                 : "=r"(r0), "=r"(r1) : "r"(addr));
}
__device__ __forceinline__ void hmma16816(float& c0, float& c1, float& c2, float& c3,
                                          const uint32_t* a, uint32_t b0, uint32_t b1) {
    asm volatile(
        "mma.sync.aligned.m16n8k16.row.col.f32.bf16.bf16.f32 "
        "{%0,%1,%2,%3}, {%4,%5,%6,%7}, {%8,%9}, {%0,%1,%2,%3};"
        : "+f"(c0), "+f"(c1), "+f"(c2), "+f"(c3)
        : "r"(a[0]), "r"(a[1]), "r"(a[2]), "r"(a[3]), "r"(b0), "r"(b1));
}

// ---------------------------------------------------------------------------
// Split-bf16 GEMM: out[t][h] = sum_k A[t][k] * B[h][k], K = 96, where
//   A k-layout: [0:32)=th, [32:64)=th, [64:96)=tl   (tok = th + tl)
//   B k-layout: [0:32)=wh, [32:64)=wl, [64:96)=wh   (W   = wh + wl)
// -> th*wh + th*wl + tl*wh  (dropped tl*wl ~ 2^-16 rel).
//
// smem rows padded to 104 bf16 (208 B): 52-word row stride keeps the 8-row
// ldmatrix address sets bank-conflict-free.
static constexpr int TILE_TOK = 128;
static constexpr int ROWB     = 208;                 // bytes per k-row
static constexpr int SW_OFF   = 0;                   // W-split: 512 rows
static constexpr int ST0      = 512 * ROWB;          // 106496
static constexpr int TBYTES   = TILE_TOK * ROWB;     // 26624
static constexpr int ST1      = ST0 + TBYTES;        // 133120
static constexpr int SMEM_TOTAL = ST1 + TBYTES;      // 159744

#define NTHREADS 512    // 16 warps: each warp owns a 32-wide H slice

__global__ __launch_bounds__(NTHREADS, 1) void fused_hmma_kernel(
    const float* __restrict__ features,   // [S, 32]
    const float* __restrict__ W,          // [32, 512]
    const float* __restrict__ b,          // [512]
    float* __restrict__ out,              // [T, 512]
    int T, int ntiles)
{
    extern __shared__ char smem[];
    const uint32_t smem_base = smem_to_u32(smem);
    const int tid  = threadIdx.x;
    const int wid  = tid >> 5;            // 0..15
    const int lane = tid & 31;

    // --- Stage W^T split into smem [h=512][k] (once per CTA) ---
    for (int idx = tid; idx < 32 * 512; idx += NTHREADS) {
        const int f = idx >> 9, h = idx & 511;       // coalesced LDG over h
        const float wv = W[idx];
        const __nv_bfloat16 hb = __float2bfloat16(wv);
        const __nv_bfloat16 lb = __float2bfloat16(wv - __bfloat162float(hb));
        char* row = smem + SW_OFF + h * ROWB;
        *(__nv_bfloat16*)(row + 2 * f)        = hb;  // wh
        *(__nv_bfloat16*)(row + 2 * (32 + f)) = lb;  // wl
        *(__nv_bfloat16*)(row + 2 * (64 + f)) = hb;  // wh
    }
    __syncthreads();

    // --- Hoist this warp's B fragments into registers (persistent) ---
    // Warp w owns h-slice [w*32, w*32+32): 4 n-tiles x 6 k-steps x 2 regs.
    const int wslice = wid * 32;
    uint32_t breg[4][6][2];
    {
        const uint32_t wb = smem_base + SW_OFF;
        #pragma unroll
        for (int nt = 0; nt < 4; nt++)
            #pragma unroll
            for (int ks = 0; ks < 6; ks++) {
                uint32_t addr = wb + (wslice + nt * 8 + (lane & 7)) * ROWB
                              + (ks * 16 + ((lane >> 3) & 1) * 8) * 2;
                ldsm_x2(breg[nt][ks][0], breg[nt][ks][1], addr);
            }
    }
    // Bias per n-tile: cols (lane&3)*2, +1 (rows r and r+8 share cols).
    float biasx[4], biasy[4];
    #pragma unroll
    for (int nt = 0; nt < 4; nt++) {
        const int col = wslice + nt * 8 + (lane & 3) * 2;
        biasx[nt] = b[col];
        biasy[nt] = b[col + 1];
    }

    int tile = blockIdx.x;
    if (tile >= ntiles) return;   // grid is clamped; defensive (uniform per CTA)

    // --- Gather: thread (f = lane, token row base = wid) ---
    const int f = lane, trow = wid;
    float ts[8];
    auto gather = [&](int tile_) {
        const int tok0 = tile_ * TILE_TOK;
        #pragma unroll
        for (int j = 0; j < 8; j++) {
            const int tok = tok0 + trow + 16 * j;
            int s0 = 0, n = 0;
            if (tok < T) { s0 = g_seg_start[tok]; n = g_seg_end[tok] - s0; }
            const float* p = features + (size_t)s0 * 32 + f;
            float a0 = (n > 0) ? p[0]  : 0.0f;
            float a1 = (n > 1) ? p[32] : 0.0f;
            float a2 = (n > 2) ? p[64] : 0.0f;
            float ex = 0.0f;
            for (int si = 3; si < n; si++) ex += p[32 * si];
            ts[j] = 1e-10f + ((a0 + a1) + (a2 + ex));
        }
    };
    auto convert_sts = [&](char* B) {
        #pragma unroll
        for (int j = 0; j < 8; j++) {
            const int r = trow + 16 * j;
            const __nv_bfloat16 hb = __float2bfloat16(ts[j]);
            const __nv_bfloat16 lb =
                __float2bfloat16(ts[j] - __bfloat162float(hb));
            char* row = B + r * ROWB;
            *(__nv_bfloat16*)(row + 2 * f)        = hb;  // th
            *(__nv_bfloat16*)(row + 2 * (32 + f)) = hb;  // th
            *(__nv_bfloat16*)(row + 2 * (64 + f)) = lb;  // tl
        }
    };

    // Prime the pipeline.
    gather(tile);
    convert_sts(smem + ST0);
    __syncthreads();

    int buf = 0;
    while (true) {
        const int next = tile + gridDim.x;
        const bool has_next = next < ntiles;

        // Prefetch next tile's gather LDGs (consumed after the MMA phase).
        if (has_next) gather(next);

        // --- MMA + store phase on current buffer ---
        const uint32_t cur = smem_base + (buf ? ST1 : ST0);
        const int tok0 = tile * TILE_TOK;
        const uint32_t arow0 = cur + (lane & 15) * ROWB + ((lane >> 4) * 8) * 2;

        #pragma unroll 1
        for (int m = 0; m < 8; m++) {
            uint32_t a[6][4];
            const uint32_t arow = arow0 + m * 16 * ROWB;
            #pragma unroll
            for (int ks = 0; ks < 6; ks++) ldsm_x4(a[ks], arow + ks * 32);

            const int r0  = tok0 + m * 16 + (lane >> 2);
            float2* o0 = reinterpret_cast<float2*>(
                out + (size_t)r0 * 512 + wslice + (lane & 3) * 2);
            float2* o1 = reinterpret_cast<float2*>(
                out + (size_t)(r0 + 8) * 512 + wslice + (lane & 3) * 2);
            const bool p0 = r0 < T, p1 = (r0 + 8) < T;

            #pragma unroll
            for (int nt = 0; nt < 4; nt++) {
                float c0 = biasx[nt], c1 = biasy[nt], c2 = c0, c3 = c1;
                #pragma unroll
                for (int ks = 0; ks < 6; ks++)
                    hmma16816(c0, c1, c2, c3, a[ks],
                              breg[nt][ks][0], breg[nt][ks][1]);
                if (p0) o0[nt * 4] = make_float2(c0, c1);
                if (p1) o1[nt * 4] = make_float2(c2, c3);
            }
        }

        // Write next tile's token buffer; one sync per tile.
        if (has_next) convert_sts(smem + (buf ? ST0 : ST1));
        __syncthreads();
        if (!has_next) break;
        tile = next;
        buf ^= 1;
    }
}

// ---------------------------------------------------------------------------
extern "C" void kernel_launch(void* const* d_in, const int* in_sizes, int n_in,
                              void* d_out, int out_size) {
    const float* features = (const float*)d_in[0];   // [S, 32]
    const float* W        = (const float*)d_in[1];   // [32, 512]
    const float* b        = (const float*)d_in[2];   // [512]
    const int*   idx      = (const int*)d_in[3];     // [S]
    float*       out      = (float*)d_out;           // [T, 512]

    const int S = in_sizes[3];
    const int T = out_size / 512;
    const int ntiles = (T + TILE_TOK - 1) / TILE_TOK;

    static int nsm = 0;
    if (nsm == 0) {
        // First call is the (non-captured) correctness run; cached afterwards.
        cudaDeviceGetAttribute(&nsm, cudaDevAttrMultiProcessorCount, 0);
        if (nsm <= 0) nsm = 148;
        cudaFuncSetAttribute(fused_hmma_kernel,
                             cudaFuncAttributeMaxDynamicSharedMemorySize,
                             SMEM_TOTAL);
    }

    seg_bounds_kernel<<<(S + 255) / 256, 256>>>(idx, S);

    int grid = nsm;
    if (grid > ntiles) grid = ntiles;
    fused_hmma_kernel<<<grid, NTHREADS, SMEM_TOTAL>>>(
        features, W, b, out, T, ntiles);
}